// round 3
// baseline (speedup 1.0000x reference)
#include <cuda_runtime.h>
#include <cuda_bf16.h>
#include <stdint.h>

#define NMAX   100000
#define EMAX   1600000
#define CINC   128
#define COUTC  64
#define CAP    96     // per-vertex slot capacity; overflow -> g_ov fixup (statistically never)

// ---------------- static device scratch (no allocation) ----------------
__device__ int   g_cur[NMAX];                       // slot cursor == in-degree after bucketing
__device__ float g_dinv[NMAX];                      // rsqrt(1+deg)
__device__ float g_H[(size_t)NMAX * COUTC];         // H = X@W + b   (25.6 MB, L2-resident)
__device__ int   g_entry[(size_t)NMAX * CAP];       // per-dst src lists (38.4 MB)
__device__ int   g_ov[EMAX];                        // overflow edge indices
__device__ int   g_ovcnt;

// ---------------- K1: zero counters ----------------
__global__ void __launch_bounds__(256) k_zero(int n) {
    int i = blockIdx.x * blockDim.x + threadIdx.x;
    if (i < n) g_cur[i] = 0;
    if (i == 0) g_ovcnt = 0;
}

// ---------------- K2: bucket edges by dst (also produces in-degree) ----------------
__global__ void __launch_bounds__(256) k_scatter(const int* __restrict__ src,
                                                 const int* __restrict__ dst, int E) {
    int e = blockIdx.x * blockDim.x + threadIdx.x;
    if (e >= E) return;
    int s = src[e], d = dst[e];
    int pos = atomicAdd(&g_cur[d], 1);
    if (pos < CAP) {
        g_entry[(size_t)d * CAP + pos] = s;
    } else {
        int o = atomicAdd(&g_ovcnt, 1);
        g_ov[o] = e;
    }
}

// ---------------- K3: dinv = rsqrt(1+deg) ----------------
__global__ void __launch_bounds__(256) k_dinv(int n) {
    int i = blockIdx.x * blockDim.x + threadIdx.x;
    if (i < n) g_dinv[i] = rsqrtf(1.0f + (float)g_cur[i]);
}

// ---------------- K4: GEMM H = X@W + b ----------------
// 256 threads, 64x64 tile, K staged in two 64-chunks (static smem ~34KB).
__global__ void __launch_bounds__(256) k_gemm(const float* __restrict__ X,
                                              const float* __restrict__ W,
                                              const float* __restrict__ b, int N) {
    __shared__ float Xs[64 * 68];   // [row][k] padded to 68
    __shared__ float Ws[64 * 64];   // [k][col]

    int tid = threadIdx.x;
    int rowBase = blockIdx.x * 64;
    int tx = tid & 15, ty = tid >> 4;       // 16x16 threads
    int r0 = ty * 4, c0 = tx * 4;           // 4x4 microtile
    float acc[4][4] = {};

    for (int kc = 0; kc < CINC; kc += 64) {
        for (int i4 = tid; i4 < 1024; i4 += 256) {          // W chunk: 64k x 64c
            int k = i4 >> 4, c4 = (i4 & 15) * 4;
            *reinterpret_cast<float4*>(&Ws[k * 64 + c4]) =
                *reinterpret_cast<const float4*>(&W[(size_t)(kc + k) * COUTC + c4]);
        }
        for (int i4 = tid; i4 < 1024; i4 += 256) {          // X chunk: 64r x 64k
            int r = i4 >> 4, k4 = (i4 & 15) * 4;
            int gr = rowBase + r;
            float4 v = make_float4(0.f, 0.f, 0.f, 0.f);
            if (gr < N) v = *reinterpret_cast<const float4*>(&X[(size_t)gr * CINC + kc + k4]);
            *reinterpret_cast<float4*>(&Xs[r * 68 + k4]) = v;
        }
        __syncthreads();

#pragma unroll 8
        for (int k = 0; k < 64; k++) {
            float a0 = Xs[(r0 + 0) * 68 + k];
            float a1 = Xs[(r0 + 1) * 68 + k];
            float a2 = Xs[(r0 + 2) * 68 + k];
            float a3 = Xs[(r0 + 3) * 68 + k];
            float4 w4 = *reinterpret_cast<const float4*>(&Ws[k * 64 + c0]);
            acc[0][0] = fmaf(a0, w4.x, acc[0][0]); acc[0][1] = fmaf(a0, w4.y, acc[0][1]);
            acc[0][2] = fmaf(a0, w4.z, acc[0][2]); acc[0][3] = fmaf(a0, w4.w, acc[0][3]);
            acc[1][0] = fmaf(a1, w4.x, acc[1][0]); acc[1][1] = fmaf(a1, w4.y, acc[1][1]);
            acc[1][2] = fmaf(a1, w4.z, acc[1][2]); acc[1][3] = fmaf(a1, w4.w, acc[1][3]);
            acc[2][0] = fmaf(a2, w4.x, acc[2][0]); acc[2][1] = fmaf(a2, w4.y, acc[2][1]);
            acc[2][2] = fmaf(a2, w4.z, acc[2][2]); acc[2][3] = fmaf(a2, w4.w, acc[2][3]);
            acc[3][0] = fmaf(a3, w4.x, acc[3][0]); acc[3][1] = fmaf(a3, w4.y, acc[3][1]);
            acc[3][2] = fmaf(a3, w4.z, acc[3][2]); acc[3][3] = fmaf(a3, w4.w, acc[3][3]);
        }
        __syncthreads();
    }

    float4 bv = *reinterpret_cast<const float4*>(&b[c0]);
#pragma unroll
    for (int i = 0; i < 4; i++) {
        int row = rowBase + r0 + i;
        if (row >= N) break;
        float4 h;
        h.x = acc[i][0] + bv.x; h.y = acc[i][1] + bv.y;
        h.z = acc[i][2] + bv.z; h.w = acc[i][3] + bv.w;
        *reinterpret_cast<float4*>(&g_H[(size_t)row * COUTC + c0]) = h;
    }
}

// ---------------- K5: warp-per-vertex pull gather + self term (+ReLU if no overflow) ----------------
__global__ void __launch_bounds__(256) k_gather(float* __restrict__ out, int N) {
    int w = (blockIdx.x * blockDim.x + threadIdx.x) >> 5;
    int lane = threadIdx.x & 31;
    if (w >= N) return;

    int cnt = g_cur[w];
    if (cnt > CAP) cnt = CAP;
    float dw = g_dinv[w];
    const int* ep = &g_entry[(size_t)w * CAP];
    int c = lane * 2;

    // lane-parallel prefetch of up to 32 (src, coef) pairs in one coalesced shot
    int   sl = 0;
    float cl = 0.0f;
    if (lane < cnt) {
        sl = ep[lane];
        cl = g_dinv[sl] * dw;
    }
    int m = cnt < 32 ? cnt : 32;

    float2 acc = make_float2(0.0f, 0.0f);
#pragma unroll 4
    for (int i = 0; i < m; i++) {
        int   s  = __shfl_sync(0xffffffffu, sl, i);
        float cf = __shfl_sync(0xffffffffu, cl, i);
        float2 h = *reinterpret_cast<const float2*>(&g_H[(size_t)s * COUTC + c]);
        acc.x = fmaf(h.x, cf, acc.x);
        acc.y = fmaf(h.y, cf, acc.y);
    }
    // rare tail: deg > 32
    for (int i = 32; i < cnt; i++) {
        int s = ep[i];
        float cf = g_dinv[s] * dw;
        float2 h = *reinterpret_cast<const float2*>(&g_H[(size_t)s * COUTC + c]);
        acc.x = fmaf(h.x, cf, acc.x);
        acc.y = fmaf(h.y, cf, acc.y);
    }

    // self-loop term
    float2 hw = *reinterpret_cast<const float2*>(&g_H[(size_t)w * COUTC + c]);
    float d2 = dw * dw;
    float2 o;
    o.x = fmaf(hw.x, d2, acc.x);
    o.y = fmaf(hw.y, d2, acc.y);

    if (g_ovcnt == 0) {           // normal path: fuse ReLU here
        o.x = fmaxf(o.x, 0.0f);
        o.y = fmaxf(o.y, 0.0f);
    }
    *reinterpret_cast<float2*>(&out[(size_t)w * COUTC + c]) = o;
}

// ---------------- K6: overflow fixup (no-op when g_ovcnt == 0) ----------------
__global__ void __launch_bounds__(256) k_overflow(const int* __restrict__ src,
                                                  const int* __restrict__ dst,
                                                  float* __restrict__ out) {
    int total = g_ovcnt;
    for (int i = blockIdx.x * blockDim.x + threadIdx.x; i < total;
         i += gridDim.x * blockDim.x) {
        int e = g_ov[i];
        int s = src[e], d = dst[e];
        float cf = g_dinv[s] * g_dinv[d];
        const float* hp = &g_H[(size_t)s * COUTC];
        float* op = &out[(size_t)d * COUTC];
#pragma unroll
        for (int ch = 0; ch < COUTC; ch++) atomicAdd(&op[ch], hp[ch] * cf);
    }
}

// ---------------- K7: deferred ReLU (no-op when g_ovcnt == 0) ----------------
__global__ void __launch_bounds__(256) k_relufix(float* __restrict__ out, int total) {
    if (g_ovcnt == 0) return;
    for (int i = blockIdx.x * blockDim.x + threadIdx.x; i < total;
         i += gridDim.x * blockDim.x) {
        out[i] = fmaxf(out[i], 0.0f);
    }
}

// ---------------- launch ----------------
extern "C" void kernel_launch(void* const* d_in, const int* in_sizes, int n_in,
                              void* d_out, int out_size) {
    const float* X   = (const float*)d_in[0];
    const float* W   = (const float*)d_in[1];
    const float* b   = (const float*)d_in[2];
    const int*   src = (const int*)d_in[3];
    const int*   dst = (const int*)d_in[4];
    float* out = (float*)d_out;

    int N = in_sizes[0] / CINC;
    int E = in_sizes[3];

    k_zero<<<(N + 255) / 256, 256>>>(N);
    k_scatter<<<(E + 255) / 256, 256>>>(src, dst, E);
    k_dinv<<<(N + 255) / 256, 256>>>(N);
    k_gemm<<<(N + 63) / 64, 256>>>(X, W, b, N);
    k_gather<<<(int)(((long long)N * 32 + 255) / 256), 256>>>(out, N);
    k_overflow<<<148, 256>>>(src, dst, out);
    k_relufix<<<296, 256>>>(out, N * COUTC);
}